// round 1
// baseline (speedup 1.0000x reference)
#include <cuda_runtime.h>
#include <math.h>

#define TB 8
#define TS 4096
#define TD 512
#define TH 2048
#define TE 8
#define TP 16
#define NTOK (TB*TS)          /* 32768 tokens */
#define APAD 136              /* padded smem row (floats), 544B = 16B-aligned, conflict-free */

/* ---------------- device state (scratch; zeroed per launch) ---------------- */
__device__ int    g_counts[TE];
__device__ int    g_base[TE];
__device__ int    g_tok[TE * NTOK];     /* token id per (expert, slot) */
__device__ float  g_gate[TE * NTOK];    /* gate weight per (expert, slot) */
__device__ double g_zsum;
__device__ double g_psum[TE];
__device__ float  g_H[(size_t)2 * NTOK * TH];   /* 65536 x 2048 fp32 = 512 MB */

/* ---------------- zero per-launch state ---------------- */
__global__ void zero_state_kernel() {
    int i = threadIdx.x;
    if (i < TE) { g_counts[i] = 0; g_psum[i] = 0.0; }
    if (i == 0) g_zsum = 0.0;
}

/* ---------------- router: logits, top-2 gates, dispatch, loss sums ----------------
   256 threads = 8 warps, each warp handles 16 tokens -> 128 tokens/block, 256 blocks. */
__global__ __launch_bounds__(256) void router_kernel(
    const float* __restrict__ x, const int* __restrict__ pid,
    const float* __restrict__ Wr, const float* __restrict__ Wp)
{
    __shared__ float sWrT[TE * TD];          /* transposed: [e][d] for conflict-free LDS */
    __shared__ float sPsum[TE];
    __shared__ float sZsum;
    __shared__ int   sCnt[TE];
    __shared__ int   sGbase[TE];
    __shared__ unsigned char sE[256];
    __shared__ short sSlot[256];
    __shared__ float sG[256];

    const int tid = threadIdx.x;
    for (int idx = tid; idx < TD * TE; idx += 256) {
        int d = idx >> 3, e = idx & 7;
        sWrT[e * TD + d] = Wr[idx];
    }
    if (tid < TE) { sPsum[tid] = 0.f; sCnt[tid] = 0; }
    if (tid == 0) sZsum = 0.f;
    __syncthreads();

    const int warp = tid >> 5, lane = tid & 31;
    const int tok0 = blockIdx.x * 128 + warp * 16;

    for (int tt = 0; tt < 16; ++tt) {
        const int t = tok0 + tt;
        float acc[TE];
        #pragma unroll
        for (int e = 0; e < TE; ++e) acc[e] = 0.f;
        const float* xr = x + (size_t)t * TD;
        for (int i = lane; i < TD; i += 32) {
            float xv = xr[i];
            #pragma unroll
            for (int e = 0; e < TE; ++e)
                acc[e] = fmaf(xv, sWrT[e * TD + i], acc[e]);
        }
        #pragma unroll
        for (int off = 16; off >= 1; off >>= 1) {
            #pragma unroll
            for (int e = 0; e < TE; ++e)
                acc[e] += __shfl_down_sync(0xffffffffu, acc[e], off);
        }
        if (lane == 0) {
            const int b = t / TS;
            const int p = pid[b];
            float l[TE];
            float zs = 0.f, mx = -1e30f;
            #pragma unroll
            for (int e = 0; e < TE; ++e) {
                l[e] = acc[e] + Wp[p * TE + e];
                zs += l[e] * l[e];
                mx = fmaxf(mx, l[e]);
            }
            atomicAdd(&sZsum, zs);
            float s = 0.f, pr[TE];
            #pragma unroll
            for (int e = 0; e < TE; ++e) { pr[e] = expf(l[e] - mx); s += pr[e]; }
            const float inv = 1.f / s;
            #pragma unroll
            for (int e = 0; e < TE; ++e) atomicAdd(&sPsum[e], pr[e] * inv);
            /* top-2 (ties -> lowest index, matching jax.lax.top_k) */
            int i0 = 0;
            #pragma unroll
            for (int e = 1; e < TE; ++e) if (l[e] > l[i0]) i0 = e;
            int i1 = (i0 == 0) ? 1 : 0;
            #pragma unroll
            for (int e = 0; e < TE; ++e) if (e != i0 && l[e] > l[i1]) i1 = e;
            const float e1 = expf(l[i1] - l[i0]);
            const float g0 = 1.f / (1.f + e1);
            const float g1 = e1 * g0;
            const int s0 = atomicAdd(&sCnt[i0], 1);
            const int s1 = atomicAdd(&sCnt[i1], 1);
            const int loc = (warp * 16 + tt) * 2;
            sE[loc]     = (unsigned char)i0; sSlot[loc]     = (short)s0; sG[loc]     = g0;
            sE[loc + 1] = (unsigned char)i1; sSlot[loc + 1] = (short)s1; sG[loc + 1] = g1;
        }
    }
    __syncthreads();
    if (tid < TE) {
        sGbase[tid] = atomicAdd(&g_counts[tid], sCnt[tid]);
        atomicAdd(&g_psum[tid], (double)sPsum[tid]);
    }
    if (tid == 0) atomicAdd(&g_zsum, (double)sZsum);
    __syncthreads();
    {
        const int e = sE[tid];
        const int pos = sGbase[e] + sSlot[tid];
        const int t = blockIdx.x * 128 + (tid >> 1);
        g_tok[e * NTOK + pos]  = t;
        g_gate[e * NTOK + pos] = sG[tid];
    }
}

/* ---------------- prefix over expert counts ---------------- */
__global__ void prefix_kernel() {
    if (threadIdx.x == 0) {
        int s = 0;
        for (int e = 0; e < TE; ++e) { g_base[e] = s; s += g_counts[e]; }
    }
}

/* ---------------- FFN stage 1: H = (X@W1) * silu(X@W3) ----------------
   grid (tiles_m=256, tiles_n=32, e=8), block 256. Tile 128(M) x 64(N), K=512.
   Per-thread 8x4 fragment, dual accumulators. */
__global__ __launch_bounds__(256, 2) void ffn1_kernel(
    const float* __restrict__ x, const float* __restrict__ W1, const float* __restrict__ W3)
{
    const int e   = blockIdx.z;
    const int cnt = g_counts[e];
    const int m0  = blockIdx.x * 128;
    if (m0 >= cnt) return;
    const int n0   = blockIdx.y * 64;
    const int base = g_base[e];

    __shared__ float As[16][APAD];
    __shared__ float B1s[16][64];
    __shared__ float B3s[16][64];
    __shared__ int stok[128];

    const int tid = threadIdx.x;
    if (tid < 128) {
        const int r = m0 + tid;
        stok[tid] = (r < cnt) ? g_tok[e * NTOK + r] : -1;
    }

    float acc1[8][4], acc3[8][4];
    #pragma unroll
    for (int i = 0; i < 8; ++i)
        #pragma unroll
        for (int j = 0; j < 4; ++j) { acc1[i][j] = 0.f; acc3[i][j] = 0.f; }

    const float* W1e = W1 + (size_t)e * TD * TH;
    const float* W3e = W3 + (size_t)e * TD * TH;
    const int tm = tid >> 4, tn = tid & 15;
    const int c4 = tid & 3, ra = tid >> 2;      /* A-tile load lanes */
    const int kr = tid >> 4, cc = tid & 15;     /* B-tile load lanes */

    for (int k0 = 0; k0 < TD; k0 += 16) {
        __syncthreads();
        #pragma unroll
        for (int j = 0; j < 2; ++j) {
            const int row = ra + 64 * j;
            const int tok = stok[row];
            float4 v = make_float4(0.f, 0.f, 0.f, 0.f);
            if (tok >= 0) v = *(const float4*)(x + (size_t)tok * TD + k0 + c4 * 4);
            As[c4 * 4 + 0][row] = v.x;
            As[c4 * 4 + 1][row] = v.y;
            As[c4 * 4 + 2][row] = v.z;
            As[c4 * 4 + 3][row] = v.w;
        }
        *(float4*)(&B1s[kr][cc * 4]) = *(const float4*)(W1e + (size_t)(k0 + kr) * TH + n0 + cc * 4);
        *(float4*)(&B3s[kr][cc * 4]) = *(const float4*)(W3e + (size_t)(k0 + kr) * TH + n0 + cc * 4);
        __syncthreads();

        #pragma unroll
        for (int k = 0; k < 16; ++k) {
            float a[8];
            *(float4*)(&a[0]) = *(const float4*)(&As[k][tm * 8]);
            *(float4*)(&a[4]) = *(const float4*)(&As[k][tm * 8 + 4]);
            const float4 b1 = *(const float4*)(&B1s[k][tn * 4]);
            const float4 b3 = *(const float4*)(&B3s[k][tn * 4]);
            #pragma unroll
            for (int i = 0; i < 8; ++i) {
                acc1[i][0] = fmaf(a[i], b1.x, acc1[i][0]);
                acc1[i][1] = fmaf(a[i], b1.y, acc1[i][1]);
                acc1[i][2] = fmaf(a[i], b1.z, acc1[i][2]);
                acc1[i][3] = fmaf(a[i], b1.w, acc1[i][3]);
                acc3[i][0] = fmaf(a[i], b3.x, acc3[i][0]);
                acc3[i][1] = fmaf(a[i], b3.y, acc3[i][1]);
                acc3[i][2] = fmaf(a[i], b3.z, acc3[i][2]);
                acc3[i][3] = fmaf(a[i], b3.w, acc3[i][3]);
            }
        }
    }

    /* epilogue: h = (X@W1) * silu(X@W3) */
    #pragma unroll
    for (int i = 0; i < 8; ++i) {
        const int r = m0 + tm * 8 + i;
        if (r < cnt) {
            float4 h;
            float v;
            v = acc3[i][0]; h.x = acc1[i][0] * (v / (1.f + expf(-v)));
            v = acc3[i][1]; h.y = acc1[i][1] * (v / (1.f + expf(-v)));
            v = acc3[i][2]; h.z = acc1[i][2] * (v / (1.f + expf(-v)));
            v = acc3[i][3]; h.w = acc1[i][3] * (v / (1.f + expf(-v)));
            *(float4*)(&g_H[(size_t)(base + r) * TH + n0 + tn * 4]) = h;
        }
    }
}

/* ---------------- FFN stage 2: y[token] += gate * (H @ W2) ----------------
   grid (tiles_m=256, tiles_n=4, e=8), block 256. Tile 128x128, K=2048, frag 8x8. */
__global__ __launch_bounds__(256, 2) void ffn2_kernel(
    const float* __restrict__ W2, float* __restrict__ y)
{
    const int e   = blockIdx.z;
    const int cnt = g_counts[e];
    const int m0  = blockIdx.x * 128;
    if (m0 >= cnt) return;
    const int n0   = blockIdx.y * 128;
    const int base = g_base[e];

    __shared__ float Hs[16][APAD];
    __shared__ float W2s[16][128];
    __shared__ int   stok[128];
    __shared__ float sgate[128];

    const int tid = threadIdx.x;
    if (tid < 128) {
        const int r = m0 + tid;
        if (r < cnt) { stok[tid] = g_tok[e * NTOK + r]; sgate[tid] = g_gate[e * NTOK + r]; }
        else         { stok[tid] = -1;                   sgate[tid] = 0.f; }
    }

    float acc[8][8];
    #pragma unroll
    for (int i = 0; i < 8; ++i)
        #pragma unroll
        for (int j = 0; j < 8; ++j) acc[i][j] = 0.f;

    const float* W2e = W2 + (size_t)e * TH * TD;
    const int tm = tid >> 4, tn = tid & 15;
    const int c4 = tid & 3, ra = tid >> 2;

    for (int k0 = 0; k0 < TH; k0 += 16) {
        __syncthreads();
        #pragma unroll
        for (int j = 0; j < 2; ++j) {
            const int row = ra + 64 * j;
            float4 v = make_float4(0.f, 0.f, 0.f, 0.f);
            if (m0 + row < cnt)
                v = *(const float4*)(&g_H[(size_t)(base + m0 + row) * TH + k0 + c4 * 4]);
            Hs[c4 * 4 + 0][row] = v.x;
            Hs[c4 * 4 + 1][row] = v.y;
            Hs[c4 * 4 + 2][row] = v.z;
            Hs[c4 * 4 + 3][row] = v.w;
        }
        #pragma unroll
        for (int j = 0; j < 2; ++j) {
            const int slot = tid + 256 * j;
            const int krw = slot >> 5, ccw = slot & 31;
            *(float4*)(&W2s[krw][ccw * 4]) =
                *(const float4*)(W2e + (size_t)(k0 + krw) * TD + n0 + ccw * 4);
        }
        __syncthreads();

        #pragma unroll
        for (int k = 0; k < 16; ++k) {
            float a[8], b[8];
            *(float4*)(&a[0]) = *(const float4*)(&Hs[k][tm * 8]);
            *(float4*)(&a[4]) = *(const float4*)(&Hs[k][tm * 8 + 4]);
            *(float4*)(&b[0]) = *(const float4*)(&W2s[k][tn * 8]);
            *(float4*)(&b[4]) = *(const float4*)(&W2s[k][tn * 8 + 4]);
            #pragma unroll
            for (int i = 0; i < 8; ++i)
                #pragma unroll
                for (int j = 0; j < 8; ++j)
                    acc[i][j] = fmaf(a[i], b[j], acc[i][j]);
        }
    }

    #pragma unroll
    for (int i = 0; i < 8; ++i) {
        const int rl = tm * 8 + i;
        if (m0 + rl < cnt) {
            const int t = stok[rl];
            const float g = sgate[rl];
            float* yr = y + (size_t)t * TD + n0 + tn * 8;
            #pragma unroll
            for (int j = 0; j < 8; ++j)
                atomicAdd(&yr[j], g * acc[i][j]);
        }
    }
}

/* ---------------- losses ---------------- */
__global__ void losses_kernel(const float* __restrict__ Wp, float* __restrict__ out, int sbase)
{
    if (threadIdx.x != 0) return;
    const double z = g_zsum / (double)((size_t)NTOK * TE) * 0.001;
    double sb = 0.0;
    for (int e = 0; e < TE; ++e) {
        const double m = g_psum[e] / (double)NTOK;
        const double d = m - 1.0 / TE;
        sb += d * d;
    }
    sb /= TE;
    float Pn[TP][TE];
    for (int p = 0; p < TP; ++p) {
        float mx = -1e30f;
        for (int e = 0; e < TE; ++e) mx = fmaxf(mx, Wp[p * TE + e]);
        float s = 0.f;
        for (int e = 0; e < TE; ++e) { Pn[p][e] = expf(Wp[p * TE + e] - mx); s += Pn[p][e]; }
        const float inv = 1.f / s;
        for (int e = 0; e < TE; ++e) Pn[p][e] *= inv;
    }
    double acc = 0.0;
    for (int p = 0; p < TP; ++p)
        for (int q = 0; q < TP; ++q)
            if (p != q) {
                float d = 0.f;
                for (int e = 0; e < TE; ++e) d += Pn[p][e] * Pn[q][e];
                acc += (double)d;
            }
    const double spec = acc / (double)(TP * TP) * 0.1;
    out[sbase + 0] = (float)z;
    out[sbase + 1] = (float)sb;
    out[sbase + 2] = (float)spec;
}

/* ---------------- launch ---------------- */
extern "C" void kernel_launch(void* const* d_in, const int* in_sizes, int n_in,
                              void* d_out, int out_size)
{
    const float* x  = (const float*)d_in[0];
    const int*   pid= (const int*)  d_in[1];
    const float* Wr = (const float*)d_in[2];
    const float* Wp = (const float*)d_in[3];
    const float* W1 = (const float*)d_in[4];
    const float* W2 = (const float*)d_in[5];
    const float* W3 = (const float*)d_in[6];
    float* out = (float*)d_out;

    cudaMemsetAsync(d_out, 0, (size_t)out_size * sizeof(float));
    zero_state_kernel<<<1, 32>>>();
    router_kernel<<<NTOK / 128, 256>>>(x, pid, Wr, Wp);
    prefix_kernel<<<1, 1>>>();

    dim3 gA(NTOK / 128, TH / 64, TE);
    ffn1_kernel<<<gA, 256>>>(x, W1, W3);

    dim3 gB(NTOK / 128, TD / 128, TE);
    ffn2_kernel<<<gB, 256>>>(W2, out);

    losses_kernel<<<1, 1>>>(Wp, out, out_size - 3);
}

// round 2
// speedup vs baseline: 2.0984x; 2.0984x over previous
#include <cuda_runtime.h>
#include <math.h>

#define TB 8
#define TS 4096
#define TD 512
#define TH 2048
#define TE 8
#define TP 16
#define NTOK (TB*TS)          /* 32768 tokens */

/* ---------------- device state (scratch; zeroed per launch) ---------------- */
__device__ int    g_counts[TE];
__device__ int    g_base[TE];
__device__ int    g_tok[TE * NTOK];
__device__ float  g_gate[TE * NTOK];
__device__ double g_zsum;
__device__ double g_psum[TE];
__device__ float  g_H[(size_t)2 * NTOK * TH];   /* 65536 x 2048 fp32 = 512 MB */

/* ---------------- helpers ---------------- */
__device__ __forceinline__ unsigned tf32_of(float f) {
    unsigned u;
    asm("cvt.rna.tf32.f32 %0, %1;" : "=r"(u) : "f"(f));
    return u;
}

__device__ __forceinline__ void mma_tf32(
    float& c0, float& c1, float& c2, float& c3,
    unsigned a0, unsigned a1, unsigned a2, unsigned a3,
    unsigned b0, unsigned b1)
{
    asm volatile(
        "mma.sync.aligned.m16n8k8.row.col.f32.tf32.tf32.f32 "
        "{%0,%1,%2,%3}, {%4,%5,%6,%7}, {%8,%9}, {%0,%1,%2,%3};"
        : "+f"(c0), "+f"(c1), "+f"(c2), "+f"(c3)
        : "r"(a0), "r"(a1), "r"(a2), "r"(a3), "r"(b0), "r"(b1));
}

/* ---------------- zero per-launch state ---------------- */
__global__ void zero_state_kernel() {
    int i = threadIdx.x;
    if (i < TE) { g_counts[i] = 0; g_psum[i] = 0.0; }
    if (i == 0) g_zsum = 0.0;
}

/* ---------------- router (unchanged from R1) ---------------- */
__global__ __launch_bounds__(256) void router_kernel(
    const float* __restrict__ x, const int* __restrict__ pid,
    const float* __restrict__ Wr, const float* __restrict__ Wp)
{
    __shared__ float sWrT[TE * TD];
    __shared__ float sPsum[TE];
    __shared__ float sZsum;
    __shared__ int   sCnt[TE];
    __shared__ int   sGbase[TE];
    __shared__ unsigned char sE[256];
    __shared__ short sSlot[256];
    __shared__ float sG[256];

    const int tid = threadIdx.x;
    for (int idx = tid; idx < TD * TE; idx += 256) {
        int d = idx >> 3, e = idx & 7;
        sWrT[e * TD + d] = Wr[idx];
    }
    if (tid < TE) { sPsum[tid] = 0.f; sCnt[tid] = 0; }
    if (tid == 0) sZsum = 0.f;
    __syncthreads();

    const int warp = tid >> 5, lane = tid & 31;
    const int tok0 = blockIdx.x * 128 + warp * 16;

    for (int tt = 0; tt < 16; ++tt) {
        const int t = tok0 + tt;
        float acc[TE];
        #pragma unroll
        for (int e = 0; e < TE; ++e) acc[e] = 0.f;
        const float* xr = x + (size_t)t * TD;
        for (int i = lane; i < TD; i += 32) {
            float xv = xr[i];
            #pragma unroll
            for (int e = 0; e < TE; ++e)
                acc[e] = fmaf(xv, sWrT[e * TD + i], acc[e]);
        }
        #pragma unroll
        for (int off = 16; off >= 1; off >>= 1) {
            #pragma unroll
            for (int e = 0; e < TE; ++e)
                acc[e] += __shfl_down_sync(0xffffffffu, acc[e], off);
        }
        if (lane == 0) {
            const int b = t / TS;
            const int p = pid[b];
            float l[TE];
            float zs = 0.f, mx = -1e30f;
            #pragma unroll
            for (int e = 0; e < TE; ++e) {
                l[e] = acc[e] + Wp[p * TE + e];
                zs += l[e] * l[e];
                mx = fmaxf(mx, l[e]);
            }
            atomicAdd(&sZsum, zs);
            float s = 0.f, pr[TE];
            #pragma unroll
            for (int e = 0; e < TE; ++e) { pr[e] = expf(l[e] - mx); s += pr[e]; }
            const float inv = 1.f / s;
            #pragma unroll
            for (int e = 0; e < TE; ++e) atomicAdd(&sPsum[e], pr[e] * inv);
            int i0 = 0;
            #pragma unroll
            for (int e = 1; e < TE; ++e) if (l[e] > l[i0]) i0 = e;
            int i1 = (i0 == 0) ? 1 : 0;
            #pragma unroll
            for (int e = 0; e < TE; ++e) if (e != i0 && l[e] > l[i1]) i1 = e;
            const float e1 = expf(l[i1] - l[i0]);
            const float g0 = 1.f / (1.f + e1);
            const float g1 = e1 * g0;
            const int s0 = atomicAdd(&sCnt[i0], 1);
            const int s1 = atomicAdd(&sCnt[i1], 1);
            const int loc = (warp * 16 + tt) * 2;
            sE[loc]     = (unsigned char)i0; sSlot[loc]     = (short)s0; sG[loc]     = g0;
            sE[loc + 1] = (unsigned char)i1; sSlot[loc + 1] = (short)s1; sG[loc + 1] = g1;
        }
    }
    __syncthreads();
    if (tid < TE) {
        sGbase[tid] = atomicAdd(&g_counts[tid], sCnt[tid]);
        atomicAdd(&g_psum[tid], (double)sPsum[tid]);
    }
    if (tid == 0) atomicAdd(&g_zsum, (double)sZsum);
    __syncthreads();
    {
        const int e = sE[tid];
        const int pos = sGbase[e] + sSlot[tid];
        const int t = blockIdx.x * 128 + (tid >> 1);
        g_tok[e * NTOK + pos]  = t;
        g_gate[e * NTOK + pos] = sG[tid];
    }
}

__global__ void prefix_kernel() {
    if (threadIdx.x == 0) {
        int s = 0;
        for (int e = 0; e < TE; ++e) { g_base[e] = s; s += g_counts[e]; }
    }
}

/* ---------------- FFN stage 1 (tf32 mma): H = (X@W1) * silu(X@W3) ----------------
   Block tile 128(M) x 64(N) x 2 gemms, BK=32, 8 warps in 4(m) x 2(n).
   Warp tile 32x32 -> 2(m) x 4(n) mma tiles per gemm. */
#define A_PAD 136
#define B_PAD 72
__global__ __launch_bounds__(256, 2) void ffn1_kernel(
    const float* __restrict__ x, const float* __restrict__ W1, const float* __restrict__ W3)
{
    const int e   = blockIdx.z;
    const int cnt = g_counts[e];
    const int m0  = blockIdx.x * 128;
    if (m0 >= cnt) return;
    const int n0   = blockIdx.y * 64;
    const int base = g_base[e];

    __shared__ unsigned As[32][A_PAD];
    __shared__ unsigned B1s[32][B_PAD];
    __shared__ unsigned B3s[32][B_PAD];
    __shared__ int stok[128];

    const int tid = threadIdx.x;
    if (tid < 128) {
        const int r = m0 + tid;
        stok[tid] = (r < cnt) ? g_tok[e * NTOK + r] : -1;
    }

    const int warp = tid >> 5, lane = tid & 31;
    const int wm = warp & 3, wn = warp >> 1 & 2 ? 0 : 0; /* placeholder */
    const int warp_m = warp & 3;            /* 0..3 -> m offset *32 */
    const int warp_n = warp >> 2;           /* 0..1 -> n offset *32 */
    (void)wm; (void)wn;
    const int lg = lane >> 2;               /* group id 0..7 */
    const int lt = lane & 3;                /* thread in group */

    float acc1[2][4][4], acc3[2][4][4];
    #pragma unroll
    for (int i = 0; i < 2; ++i)
        #pragma unroll
        for (int j = 0; j < 4; ++j)
            #pragma unroll
            for (int k = 0; k < 4; ++k) { acc1[i][j][k] = 0.f; acc3[i][j][k] = 0.f; }

    const float* W1e = W1 + (size_t)e * TD * TH;
    const float* W3e = W3 + (size_t)e * TD * TH;

    const int kq   = tid & 7;        /* A load: k quad 0..7 */
    const int arow = tid >> 3;       /* A load: base row 0..31 */

    for (int k0 = 0; k0 < TD; k0 += 32) {
        __syncthreads();
        /* load A tile (gathered X rows), transpose to As[k][m], cvt tf32 */
        #pragma unroll
        for (int j = 0; j < 4; ++j) {
            const int row = arow + 32 * j;
            const int tok = stok[row];
            float4 v = make_float4(0.f, 0.f, 0.f, 0.f);
            if (tok >= 0) v = *(const float4*)(x + (size_t)tok * TD + k0 + kq * 4);
            As[kq * 4 + 0][row] = tf32_of(v.x);
            As[kq * 4 + 1][row] = tf32_of(v.y);
            As[kq * 4 + 2][row] = tf32_of(v.z);
            As[kq * 4 + 3][row] = tf32_of(v.w);
        }
        /* load B tiles [32k x 64n] */
        #pragma unroll
        for (int j = 0; j < 2; ++j) {
            const int slot = tid + 256 * j;
            const int kr = slot >> 4, cg = slot & 15;
            float4 v1 = *(const float4*)(W1e + (size_t)(k0 + kr) * TH + n0 + cg * 4);
            float4 v3 = *(const float4*)(W3e + (size_t)(k0 + kr) * TH + n0 + cg * 4);
            B1s[kr][cg * 4 + 0] = tf32_of(v1.x);
            B1s[kr][cg * 4 + 1] = tf32_of(v1.y);
            B1s[kr][cg * 4 + 2] = tf32_of(v1.z);
            B1s[kr][cg * 4 + 3] = tf32_of(v1.w);
            B3s[kr][cg * 4 + 0] = tf32_of(v3.x);
            B3s[kr][cg * 4 + 1] = tf32_of(v3.y);
            B3s[kr][cg * 4 + 2] = tf32_of(v3.z);
            B3s[kr][cg * 4 + 3] = tf32_of(v3.w);
        }
        __syncthreads();

        #pragma unroll
        for (int ks = 0; ks < 4; ++ks) {
            const int kk = ks * 8;
            unsigned a[2][4];
            #pragma unroll
            for (int mi = 0; mi < 2; ++mi) {
                const int mr = warp_m * 32 + mi * 16;
                a[mi][0] = As[kk + lt][mr + lg];
                a[mi][1] = As[kk + lt][mr + 8 + lg];
                a[mi][2] = As[kk + 4 + lt][mr + lg];
                a[mi][3] = As[kk + 4 + lt][mr + 8 + lg];
            }
            unsigned b1f[4][2], b3f[4][2];
            #pragma unroll
            for (int ni = 0; ni < 4; ++ni) {
                const int nc = warp_n * 32 + ni * 8;
                b1f[ni][0] = B1s[kk + lt][nc + lg];
                b1f[ni][1] = B1s[kk + 4 + lt][nc + lg];
                b3f[ni][0] = B3s[kk + lt][nc + lg];
                b3f[ni][1] = B3s[kk + 4 + lt][nc + lg];
            }
            #pragma unroll
            for (int mi = 0; mi < 2; ++mi)
                #pragma unroll
                for (int ni = 0; ni < 4; ++ni) {
                    mma_tf32(acc1[mi][ni][0], acc1[mi][ni][1], acc1[mi][ni][2], acc1[mi][ni][3],
                             a[mi][0], a[mi][1], a[mi][2], a[mi][3], b1f[ni][0], b1f[ni][1]);
                    mma_tf32(acc3[mi][ni][0], acc3[mi][ni][1], acc3[mi][ni][2], acc3[mi][ni][3],
                             a[mi][0], a[mi][1], a[mi][2], a[mi][3], b3f[ni][0], b3f[ni][1]);
                }
        }
    }

    /* epilogue: h = (X@W1) * silu(X@W3), store float2 pairs */
    #pragma unroll
    for (int mi = 0; mi < 2; ++mi) {
        #pragma unroll
        for (int half = 0; half < 2; ++half) {
            const int rl = warp_m * 32 + mi * 16 + half * 8 + lg;
            const int r  = m0 + rl;
            if (r < cnt) {
                float* hrow = g_H + (size_t)(base + r) * TH;
                #pragma unroll
                for (int ni = 0; ni < 4; ++ni) {
                    const int col = n0 + warp_n * 32 + ni * 8 + 2 * lt;
                    const float g1v = acc1[mi][ni][half * 2 + 0];
                    const float g1w = acc1[mi][ni][half * 2 + 1];
                    const float g3v = acc3[mi][ni][half * 2 + 0];
                    const float g3w = acc3[mi][ni][half * 2 + 1];
                    float2 h;
                    h.x = g1v * (g3v / (1.f + expf(-g3v)));
                    h.y = g1w * (g3w / (1.f + expf(-g3w)));
                    *(float2*)(hrow + col) = h;
                }
            }
        }
    }
}

/* ---------------- FFN stage 2 (tf32 mma): y += gate * (H @ W2) ----------------
   Block tile 128x128, BK=32, 8 warps in 2(m) x 4(n). Warp tile 64x32 -> 4x4 mma. */
#define H_PAD 136
__global__ __launch_bounds__(256, 2) void ffn2_kernel(
    const float* __restrict__ W2, float* __restrict__ y)
{
    const int e   = blockIdx.z;
    const int cnt = g_counts[e];
    const int m0  = blockIdx.x * 128;
    if (m0 >= cnt) return;
    const int n0   = blockIdx.y * 128;
    const int base = g_base[e];

    __shared__ unsigned Hs[32][H_PAD];
    __shared__ unsigned W2s[32][H_PAD];
    __shared__ int   stok[128];
    __shared__ float sgate[128];

    const int tid = threadIdx.x;
    if (tid < 128) {
        const int r = m0 + tid;
        if (r < cnt) { stok[tid] = g_tok[e * NTOK + r]; sgate[tid] = g_gate[e * NTOK + r]; }
        else         { stok[tid] = -1;                   sgate[tid] = 0.f; }
    }

    const int warp = tid >> 5, lane = tid & 31;
    const int warp_m = warp & 1;   /* *64 */
    const int warp_n = warp >> 1;  /* *32 */
    const int lg = lane >> 2, lt = lane & 3;

    float acc[4][4][4];
    #pragma unroll
    for (int i = 0; i < 4; ++i)
        #pragma unroll
        for (int j = 0; j < 4; ++j)
            #pragma unroll
            for (int k = 0; k < 4; ++k) acc[i][j][k] = 0.f;

    const float* W2e = W2 + (size_t)e * TH * TD;
    const int kq = tid & 7, arow = tid >> 3;

    for (int k0 = 0; k0 < TH; k0 += 32) {
        __syncthreads();
        #pragma unroll
        for (int j = 0; j < 4; ++j) {
            const int row = arow + 32 * j;
            float4 v = make_float4(0.f, 0.f, 0.f, 0.f);
            if (m0 + row < cnt)
                v = *(const float4*)(&g_H[(size_t)(base + m0 + row) * TH + k0 + kq * 4]);
            Hs[kq * 4 + 0][row] = tf32_of(v.x);
            Hs[kq * 4 + 1][row] = tf32_of(v.y);
            Hs[kq * 4 + 2][row] = tf32_of(v.z);
            Hs[kq * 4 + 3][row] = tf32_of(v.w);
        }
        #pragma unroll
        for (int j = 0; j < 4; ++j) {
            const int slot = tid + 256 * j;
            const int kr = slot >> 5, cg = slot & 31;
            float4 v = *(const float4*)(W2e + (size_t)(k0 + kr) * TD + n0 + cg * 4);
            W2s[kr][cg * 4 + 0] = tf32_of(v.x);
            W2s[kr][cg * 4 + 1] = tf32_of(v.y);
            W2s[kr][cg * 4 + 2] = tf32_of(v.z);
            W2s[kr][cg * 4 + 3] = tf32_of(v.w);
        }
        __syncthreads();

        #pragma unroll
        for (int ks = 0; ks < 4; ++ks) {
            const int kk = ks * 8;
            unsigned a[4][4];
            #pragma unroll
            for (int mi = 0; mi < 4; ++mi) {
                const int mr = warp_m * 64 + mi * 16;
                a[mi][0] = Hs[kk + lt][mr + lg];
                a[mi][1] = Hs[kk + lt][mr + 8 + lg];
                a[mi][2] = Hs[kk + 4 + lt][mr + lg];
                a[mi][3] = Hs[kk + 4 + lt][mr + 8 + lg];
            }
            unsigned b[4][2];
            #pragma unroll
            for (int ni = 0; ni < 4; ++ni) {
                const int nc = warp_n * 32 + ni * 8;
                b[ni][0] = W2s[kk + lt][nc + lg];
                b[ni][1] = W2s[kk + 4 + lt][nc + lg];
            }
            #pragma unroll
            for (int mi = 0; mi < 4; ++mi)
                #pragma unroll
                for (int ni = 0; ni < 4; ++ni)
                    mma_tf32(acc[mi][ni][0], acc[mi][ni][1], acc[mi][ni][2], acc[mi][ni][3],
                             a[mi][0], a[mi][1], a[mi][2], a[mi][3], b[ni][0], b[ni][1]);
        }
    }

    #pragma unroll
    for (int mi = 0; mi < 4; ++mi) {
        #pragma unroll
        for (int half = 0; half < 2; ++half) {
            const int rl = warp_m * 64 + mi * 16 + half * 8 + lg;
            if (m0 + rl < cnt) {
                const int t = stok[rl];
                const float g = sgate[rl];
                float* yr = y + (size_t)t * TD + n0 + warp_n * 32;
                #pragma unroll
                for (int ni = 0; ni < 4; ++ni) {
                    const int col = ni * 8 + 2 * lt;
                    atomicAdd(&yr[col],     g * acc[mi][ni][half * 2 + 0]);
                    atomicAdd(&yr[col + 1], g * acc[mi][ni][half * 2 + 1]);
                }
            }
        }
    }
}

/* ---------------- losses ---------------- */
__global__ void losses_kernel(const float* __restrict__ Wp, float* __restrict__ out, int sbase)
{
    if (threadIdx.x != 0) return;
    const double z = g_zsum / (double)((size_t)NTOK * TE) * 0.001;
    double sb = 0.0;
    for (int e = 0; e < TE; ++e) {
        const double m = g_psum[e] / (double)NTOK;
        const double d = m - 1.0 / TE;
        sb += d * d;
    }
    sb /= TE;
    float Pn[TP][TE];
    for (int p = 0; p < TP; ++p) {
        float mx = -1e30f;
        for (int e = 0; e < TE; ++e) mx = fmaxf(mx, Wp[p * TE + e]);
        float s = 0.f;
        for (int e = 0; e < TE; ++e) { Pn[p][e] = expf(Wp[p * TE + e] - mx); s += Pn[p][e]; }
        const float inv = 1.f / s;
        for (int e = 0; e < TE; ++e) Pn[p][e] *= inv;
    }
    double acc = 0.0;
    for (int p = 0; p < TP; ++p)
        for (int q = 0; q < TP; ++q)
            if (p != q) {
                float d = 0.f;
                for (int e = 0; e < TE; ++e) d += Pn[p][e] * Pn[q][e];
                acc += (double)d;
            }
    const double spec = acc / (double)(TP * TP) * 0.1;
    out[sbase + 0] = (float)z;
    out[sbase + 1] = (float)sb;
    out[sbase + 2] = (float)spec;
}

/* ---------------- launch ---------------- */
extern "C" void kernel_launch(void* const* d_in, const int* in_sizes, int n_in,
                              void* d_out, int out_size)
{
    const float* x  = (const float*)d_in[0];
    const int*   pid= (const int*)  d_in[1];
    const float* Wr = (const float*)d_in[2];
    const float* Wp = (const float*)d_in[3];
    const float* W1 = (const float*)d_in[4];
    const float* W2 = (const float*)d_in[5];
    const float* W3 = (const float*)d_in[6];
    float* out = (float*)d_out;

    cudaMemsetAsync(d_out, 0, (size_t)out_size * sizeof(float));
    zero_state_kernel<<<1, 32>>>();
    router_kernel<<<NTOK / 128, 256>>>(x, pid, Wr, Wp);
    prefix_kernel<<<1, 1>>>();

    dim3 gA(NTOK / 128, TH / 64, TE);
    ffn1_kernel<<<gA, 256>>>(x, W1, W3);

    dim3 gB(NTOK / 128, TD / 128, TE);
    ffn2_kernel<<<gB, 256>>>(W2, out);

    losses_kernel<<<1, 1>>>(Wp, out, out_size - 3);
}

// round 3
// speedup vs baseline: 3.8278x; 1.8241x over previous
#include <cuda_runtime.h>
#include <math.h>

#define TB 8
#define TS 4096
#define TD 512
#define TH 2048
#define TE 8
#define TP 16
#define NTOK (TB*TS)          /* 32768 tokens */

/* ---------------- device state (scratch; rewritten every launch) ---------------- */
__device__ int    g_counts[TE];
__device__ int    g_base[TE];
__device__ int    g_tok[TE * NTOK];
__device__ float  g_gate[TE * NTOK];
__device__ double g_zsum;
__device__ double g_psum[TE];
__device__ float  g_H[(size_t)2 * NTOK * TH];     /* 512 MB, tf32-rounded values */
__device__ float  g_xt[(size_t)NTOK * TD];        /* tf32-rounded x */
__device__ float  g_w1t[(size_t)TE * TD * TH];
__device__ float  g_w3t[(size_t)TE * TD * TH];
__device__ float  g_w2t[(size_t)TE * TH * TD];

/* ---------------- helpers ---------------- */
__device__ __forceinline__ unsigned tf32_of(float f) {
    unsigned u;
    asm("cvt.rna.tf32.f32 %0, %1;" : "=r"(u) : "f"(f));
    return u;
}
__device__ __forceinline__ float tf32f(float f) { return __uint_as_float(tf32_of(f)); }

__device__ __forceinline__ void mma_tf32(
    float& c0, float& c1, float& c2, float& c3,
    unsigned a0, unsigned a1, unsigned a2, unsigned a3,
    unsigned b0, unsigned b1)
{
    asm volatile(
        "mma.sync.aligned.m16n8k8.row.col.f32.tf32.tf32.f32 "
        "{%0,%1,%2,%3}, {%4,%5,%6,%7}, {%8,%9}, {%0,%1,%2,%3};"
        : "+f"(c0), "+f"(c1), "+f"(c2), "+f"(c3)
        : "r"(a0), "r"(a1), "r"(a2), "r"(a3), "r"(b0), "r"(b1));
}

#define CP16(dst, src) \
    asm volatile("cp.async.cg.shared.global [%0], [%1], 16;" :: "r"(dst), "l"(src))
#define CP_COMMIT() asm volatile("cp.async.commit_group;")
#define CP_WAIT1()  asm volatile("cp.async.wait_group 1;")
#define CP_WAIT0()  asm volatile("cp.async.wait_group 0;")

__device__ __forceinline__ unsigned sptr(const void* p) {
    return (unsigned)__cvta_generic_to_shared(p);
}

/* ---------------- zero per-launch state ---------------- */
__global__ void zero_state_kernel() {
    int i = threadIdx.x;
    if (i < TE) { g_counts[i] = 0; g_psum[i] = 0.0; }
    if (i == 0) g_zsum = 0.0;
}

/* ---------------- pre-convert x, W1, W3, W2 to tf32-rounded fp32 ---------------- */
__global__ __launch_bounds__(256) void precvt_kernel(
    const float* __restrict__ x, const float* __restrict__ W1,
    const float* __restrict__ W2, const float* __restrict__ W3)
{
    const size_t NX = (size_t)NTOK * TD / 4;
    const size_t NW = (size_t)TE * TD * TH / 4;
    size_t i = (size_t)blockIdx.x * 256 + threadIdx.x;
    const size_t stride = (size_t)gridDim.x * 256;
    for (; i < NX + 3 * NW; i += stride) {
        const float4* src; float4* dst; size_t j;
        if (i < NX)                { src = (const float4*)x;  dst = (float4*)g_xt;  j = i; }
        else if (i < NX + NW)      { src = (const float4*)W1; dst = (float4*)g_w1t; j = i - NX; }
        else if (i < NX + 2 * NW)  { src = (const float4*)W3; dst = (float4*)g_w3t; j = i - NX - NW; }
        else                       { src = (const float4*)W2; dst = (float4*)g_w2t; j = i - NX - 2 * NW; }
        float4 v = src[j];
        v.x = tf32f(v.x); v.y = tf32f(v.y); v.z = tf32f(v.z); v.w = tf32f(v.w);
        dst[j] = v;
    }
}

/* ---------------- router (reads original fp32 x; unchanged, passing) ---------------- */
__global__ __launch_bounds__(256) void router_kernel(
    const float* __restrict__ x, const int* __restrict__ pid,
    const float* __restrict__ Wr, const float* __restrict__ Wp)
{
    __shared__ float sWrT[TE * TD];
    __shared__ float sPsum[TE];
    __shared__ float sZsum;
    __shared__ int   sCnt[TE];
    __shared__ int   sGbase[TE];
    __shared__ unsigned char sE[256];
    __shared__ short sSlot[256];
    __shared__ float sG[256];

    const int tid = threadIdx.x;
    for (int idx = tid; idx < TD * TE; idx += 256) {
        int d = idx >> 3, e = idx & 7;
        sWrT[e * TD + d] = Wr[idx];
    }
    if (tid < TE) { sPsum[tid] = 0.f; sCnt[tid] = 0; }
    if (tid == 0) sZsum = 0.f;
    __syncthreads();

    const int warp = tid >> 5, lane = tid & 31;
    const int tok0 = blockIdx.x * 128 + warp * 16;

    for (int tt = 0; tt < 16; ++tt) {
        const int t = tok0 + tt;
        float acc[TE];
        #pragma unroll
        for (int e = 0; e < TE; ++e) acc[e] = 0.f;
        const float* xr = x + (size_t)t * TD;
        for (int i = lane; i < TD; i += 32) {
            float xv = xr[i];
            #pragma unroll
            for (int e = 0; e < TE; ++e)
                acc[e] = fmaf(xv, sWrT[e * TD + i], acc[e]);
        }
        #pragma unroll
        for (int off = 16; off >= 1; off >>= 1) {
            #pragma unroll
            for (int e = 0; e < TE; ++e)
                acc[e] += __shfl_down_sync(0xffffffffu, acc[e], off);
        }
        if (lane == 0) {
            const int b = t / TS;
            const int p = pid[b];
            float l[TE];
            float zs = 0.f, mx = -1e30f;
            #pragma unroll
            for (int e = 0; e < TE; ++e) {
                l[e] = acc[e] + Wp[p * TE + e];
                zs += l[e] * l[e];
                mx = fmaxf(mx, l[e]);
            }
            atomicAdd(&sZsum, zs);
            float s = 0.f, pr[TE];
            #pragma unroll
            for (int e = 0; e < TE; ++e) { pr[e] = expf(l[e] - mx); s += pr[e]; }
            const float inv = 1.f / s;
            #pragma unroll
            for (int e = 0; e < TE; ++e) atomicAdd(&sPsum[e], pr[e] * inv);
            int i0 = 0;
            #pragma unroll
            for (int e = 1; e < TE; ++e) if (l[e] > l[i0]) i0 = e;
            int i1 = (i0 == 0) ? 1 : 0;
            #pragma unroll
            for (int e = 0; e < TE; ++e) if (e != i0 && l[e] > l[i1]) i1 = e;
            const float e1 = expf(l[i1] - l[i0]);
            const float g0 = 1.f / (1.f + e1);
            const float g1 = e1 * g0;
            const int s0 = atomicAdd(&sCnt[i0], 1);
            const int s1 = atomicAdd(&sCnt[i1], 1);
            const int loc = (warp * 16 + tt) * 2;
            sE[loc]     = (unsigned char)i0; sSlot[loc]     = (short)s0; sG[loc]     = g0;
            sE[loc + 1] = (unsigned char)i1; sSlot[loc + 1] = (short)s1; sG[loc + 1] = g1;
        }
    }
    __syncthreads();
    if (tid < TE) {
        sGbase[tid] = atomicAdd(&g_counts[tid], sCnt[tid]);
        atomicAdd(&g_psum[tid], (double)sPsum[tid]);
    }
    if (tid == 0) atomicAdd(&g_zsum, (double)sZsum);
    __syncthreads();
    {
        const int e = sE[tid];
        const int pos = sGbase[e] + sSlot[tid];
        const int t = blockIdx.x * 128 + (tid >> 1);
        g_tok[e * NTOK + pos]  = t;
        g_gate[e * NTOK + pos] = sG[tid];
    }
}

__global__ void prefix_kernel() {
    if (threadIdx.x == 0) {
        int s = 0;
        for (int e = 0; e < TE; ++e) { g_base[e] = s; s += g_counts[e]; }
    }
}

/* ================= FFN stage 1: H = (X@W1) * silu(X@W3) =================
   Block 128(M) x 64(N), BK=32, 16 k-iters, 3-stage cp.async pipeline.
   Smem: Xs[3][128][32] xor-swizzled, B1s/B3s[3][32][72] (stride 72 -> conflict-free).
   8 warps 4(m) x 2(n); warp tile 32x32 per gemm. */
#define X_STG  (128 * 32)      /* 4096 floats per stage */
#define B1_STG (32 * 72)       /* 2304 floats per stage */
#define FFN1_SMEM ((3 * X_STG + 3 * B1_STG + 3 * B1_STG) * 4 + 128 * 4)

__global__ __launch_bounds__(256, 2) void ffn1_kernel()
{
    const int e   = blockIdx.z;
    const int cnt = g_counts[e];
    const int m0  = blockIdx.x * 128;
    if (m0 >= cnt) return;
    const int n0   = blockIdx.y * 64;
    const int base = g_base[e];

    extern __shared__ float smem[];
    float* Xs  = smem;                       /* 3 * 4096 */
    float* B1s = smem + 3 * X_STG;           /* 3 * 2304 */
    float* B3s = B1s + 3 * B1_STG;           /* 3 * 2304 */
    int*   stok = (int*)(B3s + 3 * B1_STG);  /* 128 */

    const int tid = threadIdx.x;
    if (tid < 128) {
        const int r = m0 + tid;
        stok[tid] = (r < cnt) ? g_tok[e * NTOK + r] : g_tok[e * NTOK];  /* clamp: pad rows read a valid row */
    }
    __syncthreads();

    const float* W1e = g_w1t + (size_t)e * TD * TH;
    const float* W3e = g_w3t + (size_t)e * TD * TH;

    const int warp = tid >> 5, lane = tid & 31;
    const int warp_m = warp & 3;     /* *32 */
    const int warp_n = warp >> 2;    /* *32 */
    const int lg = lane >> 2, lt = lane & 3;

    /* ---- cp.async stage issue ---- */
    auto issue = [&](int it, int stg) {
        const int k0 = it * 32;
        float* Xd  = Xs  + stg * X_STG;
        float* B1d = B1s + stg * B1_STG;
        float* B3d = B3s + stg * B1_STG;
        #pragma unroll
        for (int j = 0; j < 4; ++j) {            /* X: 1024 chunks of 16B */
            const int q = tid + 256 * j;
            const int r = q >> 3, c = q & 7;
            const float* src = g_xt + (size_t)stok[r] * TD + k0 + c * 4;
            CP16(sptr(Xd + r * 32 + ((c ^ (r & 7)) << 2)), src);
        }
        #pragma unroll
        for (int j = 0; j < 2; ++j) {            /* B1,B3: 512 chunks each */
            const int q = tid + 256 * j;
            const int k = q >> 4, n4 = q & 15;
            CP16(sptr(B1d + k * 72 + n4 * 4), W1e + (size_t)(k0 + k) * TH + n0 + n4 * 4);
            CP16(sptr(B3d + k * 72 + n4 * 4), W3e + (size_t)(k0 + k) * TH + n0 + n4 * 4);
        }
        CP_COMMIT();
    };

    float acc1[2][4][4], acc3[2][4][4];
    #pragma unroll
    for (int i = 0; i < 2; ++i)
        #pragma unroll
        for (int j = 0; j < 4; ++j)
            #pragma unroll
            for (int k = 0; k < 4; ++k) { acc1[i][j][k] = 0.f; acc3[i][j][k] = 0.f; }

    issue(0, 0);
    issue(1, 1);
    int sa = 0, sc = 2;
    const int NIT = TD / 32;   /* 16 */

    #pragma unroll 1
    for (int it = 0; it < NIT; ++it) {
        if (it < NIT - 1) { CP_WAIT1(); } else { CP_WAIT0(); }
        __syncthreads();

        const float* Xc  = Xs  + sa * X_STG;
        const float* B1c = B1s + sa * B1_STG;
        const float* B3c = B3s + sa * B1_STG;

        #pragma unroll
        for (int ks = 0; ks < 4; ++ks) {
            const int kk = ks * 8;
            const int c0 = kk >> 2;
            unsigned a[2][4];
            #pragma unroll
            for (int mi = 0; mi < 2; ++mi) {
                const int r0 = warp_m * 32 + mi * 16 + lg;
                const float* row0 = Xc + r0 * 32;
                const float* row1 = row0 + 8 * 32;
                const int o0 = ((c0 ^ lg) << 2) + lt;
                const int o1 = (((c0 + 1) ^ lg) << 2) + lt;
                a[mi][0] = __float_as_uint(row0[o0]);
                a[mi][1] = __float_as_uint(row1[o0]);
                a[mi][2] = __float_as_uint(row0[o1]);
                a[mi][3] = __float_as_uint(row1[o1]);
            }
            const float* b1k0 = B1c + (kk + lt) * 72;
            const float* b1k1 = b1k0 + 4 * 72;
            const float* b3k0 = B3c + (kk + lt) * 72;
            const float* b3k1 = b3k0 + 4 * 72;
            unsigned b1f[4][2], b3f[4][2];
            #pragma unroll
            for (int ni = 0; ni < 4; ++ni) {
                const int nc = warp_n * 32 + ni * 8 + lg;
                b1f[ni][0] = __float_as_uint(b1k0[nc]);
                b1f[ni][1] = __float_as_uint(b1k1[nc]);
                b3f[ni][0] = __float_as_uint(b3k0[nc]);
                b3f[ni][1] = __float_as_uint(b3k1[nc]);
            }
            #pragma unroll
            for (int mi = 0; mi < 2; ++mi)
                #pragma unroll
                for (int ni = 0; ni < 4; ++ni) {
                    mma_tf32(acc1[mi][ni][0], acc1[mi][ni][1], acc1[mi][ni][2], acc1[mi][ni][3],
                             a[mi][0], a[mi][1], a[mi][2], a[mi][3], b1f[ni][0], b1f[ni][1]);
                    mma_tf32(acc3[mi][ni][0], acc3[mi][ni][1], acc3[mi][ni][2], acc3[mi][ni][3],
                             a[mi][0], a[mi][1], a[mi][2], a[mi][3], b3f[ni][0], b3f[ni][1]);
                }
        }

        if (it + 2 < NIT) issue(it + 2, sc);
        if (++sa == 3) sa = 0;
        if (++sc == 3) sc = 0;
    }

    /* epilogue: h = (X@W1) * silu(X@W3), tf32-rounded so ffn2 loads it raw */
    #pragma unroll
    for (int mi = 0; mi < 2; ++mi) {
        #pragma unroll
        for (int half = 0; half < 2; ++half) {
            const int rl = warp_m * 32 + mi * 16 + half * 8 + lg;
            const int r  = m0 + rl;
            if (r < cnt) {
                float* hrow = g_H + (size_t)(base + r) * TH;
                #pragma unroll
                for (int ni = 0; ni < 4; ++ni) {
                    const int col = n0 + warp_n * 32 + ni * 8 + 2 * lt;
                    const float g1v = acc1[mi][ni][half * 2 + 0];
                    const float g1w = acc1[mi][ni][half * 2 + 1];
                    const float g3v = acc3[mi][ni][half * 2 + 0];
                    const float g3w = acc3[mi][ni][half * 2 + 1];
                    float2 h;
                    h.x = tf32f(g1v * (g3v / (1.f + expf(-g3v))));
                    h.y = tf32f(g1w * (g3w / (1.f + expf(-g3w))));
                    *(float2*)(hrow + col) = h;
                }
            }
        }
    }
}

/* ================= FFN stage 2: y += gate * (H @ W2) =================
   Block 128x128, BK=32, 64 k-iters, 3-stage cp.async pipeline.
   Smem: Hs[3][128][32] xor-swizzled, W2s[3][32][136].
   8 warps 2(m) x 4(n); warp tile 64x32. */
#define H_STG  (128 * 32)
#define W2_STG (32 * 136)
#define FFN2_SMEM ((3 * H_STG + 3 * W2_STG) * 4 + 128 * 4 + 128 * 4)

__global__ __launch_bounds__(256, 2) void ffn2_kernel(float* __restrict__ y)
{
    const int e   = blockIdx.z;
    const int cnt = g_counts[e];
    const int m0  = blockIdx.x * 128;
    if (m0 >= cnt) return;
    const int n0   = blockIdx.y * 128;
    const int base = g_base[e];

    extern __shared__ float smem[];
    float* Hs  = smem;                        /* 3 * 4096 */
    float* W2s = smem + 3 * H_STG;            /* 3 * 4352 */
    int*   stok  = (int*)(W2s + 3 * W2_STG);  /* 128 */
    float* sgate = (float*)(stok + 128);      /* 128 */
    int*   shrow = (int*)(sgate + 128);       /* reuse? no — need separate; pack after sgate */

    const int tid = threadIdx.x;
    if (tid < 128) {
        const int r = m0 + tid;
        if (r < cnt) { stok[tid] = g_tok[e * NTOK + r]; sgate[tid] = g_gate[e * NTOK + r]; }
        else         { stok[tid] = -1;                   sgate[tid] = 0.f; }
    }
    __syncthreads();
    (void)shrow;

    const float* W2e = g_w2t + (size_t)e * TH * TD;
    const int cm1 = cnt - 1;

    const int warp = tid >> 5, lane = tid & 31;
    const int warp_m = warp & 1;    /* *64 */
    const int warp_n = warp >> 1;   /* *32 */
    const int lg = lane >> 2, lt = lane & 3;

    auto issue = [&](int it, int stg) {
        const int k0 = it * 32;
        float* Hd  = Hs  + stg * H_STG;
        float* W2d = W2s + stg * W2_STG;
        #pragma unroll
        for (int j = 0; j < 4; ++j) {           /* H: 1024 chunks */
            const int q = tid + 256 * j;
            const int r = q >> 3, c = q & 7;
            const int grow = base + min(m0 + r, cm1);
            const float* src = g_H + (size_t)grow * TH + k0 + c * 4;
            CP16(sptr(Hd + r * 32 + ((c ^ (r & 7)) << 2)), src);
        }
        #pragma unroll
        for (int j = 0; j < 4; ++j) {           /* W2: 1024 chunks */
            const int q = tid + 256 * j;
            const int k = q >> 5, n4 = q & 31;
            CP16(sptr(W2d + k * 136 + n4 * 4), W2e + (size_t)(k0 + k) * TD + n0 + n4 * 4);
        }
        CP_COMMIT();
    };

    float acc[4][4][4];
    #pragma unroll
    for (int i = 0; i < 4; ++i)
        #pragma unroll
        for (int j = 0; j < 4; ++j)
            #pragma unroll
            for (int k = 0; k < 4; ++k) acc[i][j][k] = 0.f;

    issue(0, 0);
    issue(1, 1);
    int sa = 0, sc = 2;
    const int NIT = TH / 32;   /* 64 */

    #pragma unroll 1
    for (int it = 0; it < NIT; ++it) {
        if (it < NIT - 1) { CP_WAIT1(); } else { CP_WAIT0(); }
        __syncthreads();

        const float* Hc  = Hs  + sa * H_STG;
        const float* W2c = W2s + sa * W2_STG;

        #pragma unroll
        for (int ks = 0; ks < 4; ++ks) {
            const int kk = ks * 8;
            const int c0 = kk >> 2;
            unsigned a[4][4];
            #pragma unroll
            for (int mi = 0; mi < 4; ++mi) {
                const int r0 = warp_m * 64 + mi * 16 + lg;
                const float* row0 = Hc + r0 * 32;
                const float* row1 = row0 + 8 * 32;
                const int o0 = ((c0 ^ lg) << 2) + lt;
                const int o1 = (((c0 + 1) ^ lg) << 2) + lt;
                a[mi][0] = __float_as_uint(row0[o0]);
                a[mi][1] = __float_as_uint(row1[o0]);
                a[mi][2] = __float_as_uint(row0[o1]);
                a[mi][3] = __float_as_uint(row1[o1]);
            }
            const float* bk0 = W2c + (kk + lt) * 136;
            const float* bk1 = bk0 + 4 * 136;
            unsigned b[4][2];
            #pragma unroll
            for (int ni = 0; ni < 4; ++ni) {
                const int nc = warp_n * 32 + ni * 8 + lg;
                b[ni][0] = __float_as_uint(bk0[nc]);
                b[ni][1] = __float_as_uint(bk1[nc]);
            }
            #pragma unroll
            for (int mi = 0; mi < 4; ++mi)
                #pragma unroll
                for (int ni = 0; ni < 4; ++ni)
                    mma_tf32(acc[mi][ni][0], acc[mi][ni][1], acc[mi][ni][2], acc[mi][ni][3],
                             a[mi][0], a[mi][1], a[mi][2], a[mi][3], b[ni][0], b[ni][1]);
        }

        if (it + 2 < NIT) issue(it + 2, sc);
        if (++sa == 3) sa = 0;
        if (++sc == 3) sc = 0;
    }

    #pragma unroll
    for (int mi = 0; mi < 4; ++mi) {
        #pragma unroll
        for (int half = 0; half < 2; ++half) {
            const int rl = warp_m * 64 + mi * 16 + half * 8 + lg;
            if (m0 + rl < cnt) {
                const int t = stok[rl];
                const float g = sgate[rl];
                float* yr = y + (size_t)t * TD + n0 + warp_n * 32;
                #pragma unroll
                for (int ni = 0; ni < 4; ++ni) {
                    const int col = ni * 8 + 2 * lt;
                    atomicAdd(&yr[col],     g * acc[mi][ni][half * 2 + 0]);
                    atomicAdd(&yr[col + 1], g * acc[mi][ni][half * 2 + 1]);
                }
            }
        }
    }
}

/* ---------------- losses ---------------- */
__global__ void losses_kernel(const float* __restrict__ Wp, float* __restrict__ out, int sbase)
{
    if (threadIdx.x != 0) return;
    const double z = g_zsum / (double)((size_t)NTOK * TE) * 0.001;
    double sb = 0.0;
    for (int e = 0; e < TE; ++e) {
        const double m = g_psum[e] / (double)NTOK;
        const double d = m - 1.0 / TE;
        sb += d * d;
    }
    sb /= TE;
    float Pn[TP][TE];
    for (int p = 0; p < TP; ++p) {
        float mx = -1e30f;
        for (int e = 0; e < TE; ++e) mx = fmaxf(mx, Wp[p * TE + e]);
        float s = 0.f;
        for (int e = 0; e < TE; ++e) { Pn[p][e] = expf(Wp[p * TE + e] - mx); s += Pn[p][e]; }
        const float inv = 1.f / s;
        for (int e = 0; e < TE; ++e) Pn[p][e] *= inv;
    }
    double acc = 0.0;
    for (int p = 0; p < TP; ++p)
        for (int q = 0; q < TP; ++q)
            if (p != q) {
                float d = 0.f;
                for (int e = 0; e < TE; ++e) d += Pn[p][e] * Pn[q][e];
                acc += (double)d;
            }
    const double spec = acc / (double)(TP * TP) * 0.1;
    out[sbase + 0] = (float)z;
    out[sbase + 1] = (float)sb;
    out[sbase + 2] = (float)spec;
}

/* ---------------- launch ---------------- */
extern "C" void kernel_launch(void* const* d_in, const int* in_sizes, int n_in,
                              void* d_out, int out_size)
{
    const float* x  = (const float*)d_in[0];
    const int*   pid= (const int*)  d_in[1];
    const float* Wr = (const float*)d_in[2];
    const float* Wp = (const float*)d_in[3];
    const float* W1 = (const float*)d_in[4];
    const float* W2 = (const float*)d_in[5];
    const float* W3 = (const float*)d_in[6];
    float* out = (float*)d_out;

    static int attr_done = 0;
    if (!attr_done) {
        cudaFuncSetAttribute(ffn1_kernel, cudaFuncAttributeMaxDynamicSharedMemorySize, FFN1_SMEM);
        cudaFuncSetAttribute(ffn2_kernel, cudaFuncAttributeMaxDynamicSharedMemorySize, FFN2_SMEM);
        attr_done = 1;
    }

    cudaMemsetAsync(d_out, 0, (size_t)out_size * sizeof(float));
    zero_state_kernel<<<1, 32>>>();
    precvt_kernel<<<16384, 256>>>(x, W1, W2, W3);
    router_kernel<<<NTOK / 128, 256>>>(x, pid, Wr, Wp);
    prefix_kernel<<<1, 1>>>();

    dim3 gA(NTOK / 128, TH / 64, TE);
    ffn1_kernel<<<gA, 256, FFN1_SMEM>>>();

    dim3 gB(NTOK / 128, TD / 128, TE);
    ffn2_kernel<<<gB, 256, FFN2_SMEM>>>(out);

    losses_kernel<<<1, 1>>>(Wp, out, out_size - 3);
}